// round 15
// baseline (speedup 1.0000x reference)
#include <cuda_runtime.h>
#include <cstdint>

#define HW 784
#define IMG_W 28
#define NTOT (32 * 784)     // 25088 = 196 * 128
#define MT 128
#define NT 128

#define AR    144                 // A row: 64B hi + 64B lo + 16B pad
#define ATILE (128 * AR)          // 18432
#define BR0   528                 // MODE0 B row: 256B hi + 256B lo + 16B pad
#define BT0   (32 * BR0)          // 16896
#define BR1   144                 // MODE1 B row: 64B hi + 64B lo + 16B pad
#define BT1   (128 * BR1)         // 18432

// ---------------------------------------------------------------------------
// Scratch (__device__ globals; allocation-free rule)
// ---------------------------------------------------------------------------
__device__ float    g_y1  [32u * 256u * 784u];       // conv1 out (fp32, relu)
__device__ uint16_t g_xh  [32u * 1024u * 784u];      // x split hi
__device__ uint16_t g_xl  [32u * 1024u * 784u];      // x split lo
__device__ uint16_t g_w1h [256u * 1024u], g_w1l[256u * 1024u];
__device__ uint16_t g_wdh [256u * 2304u], g_wdl[256u * 2304u];   // K-reordered
__device__ uint16_t g_w3h [1024u * 256u], g_w3l[1024u * 256u];
__device__ uint16_t g_y1th[32u * 784u * 256u], g_y1tl[32u * 784u * 256u]; // shuffled, transposed
__device__ uint16_t g_y2h [32u * 256u * 784u], g_y2l[32u * 256u * 784u]; // dconv out

// ---------------------------------------------------------------------------
// PTX helpers (sm_80+ baseline only)
// ---------------------------------------------------------------------------
__device__ __forceinline__ uint32_t smem_to_u32(const void* p) {
    uint32_t a;
    asm("{ .reg .u64 t; cvta.to.shared.u64 t, %1; cvt.u32.u64 %0, t; }" : "=r"(a) : "l"(p));
    return a;
}
__device__ __forceinline__ void ldsm4(uint32_t* r, uint32_t a) {
    asm volatile("ldmatrix.sync.aligned.m8n8.x4.shared.b16 {%0,%1,%2,%3}, [%4];"
                 : "=r"(r[0]), "=r"(r[1]), "=r"(r[2]), "=r"(r[3]) : "r"(a));
}
__device__ __forceinline__ void ldsm4t(uint32_t* r, uint32_t a) {
    asm volatile("ldmatrix.sync.aligned.m8n8.x4.trans.shared.b16 {%0,%1,%2,%3}, [%4];"
                 : "=r"(r[0]), "=r"(r[1]), "=r"(r[2]), "=r"(r[3]) : "r"(a));
}
__device__ __forceinline__ void mma_bf16(float* d, const uint32_t* a, const uint32_t* b) {
    asm volatile(
        "mma.sync.aligned.m16n8k16.row.col.f32.bf16.bf16.f32 "
        "{%0,%1,%2,%3}, {%4,%5,%6,%7}, {%8,%9}, {%0,%1,%2,%3};"
        : "+f"(d[0]), "+f"(d[1]), "+f"(d[2]), "+f"(d[3])
        : "r"(a[0]), "r"(a[1]), "r"(a[2]), "r"(a[3]), "r"(b[0]), "r"(b[1]));
}
__device__ __forceinline__ uint32_t pack_bf16x2(float a, float b) {
    uint32_t r;
    asm("cvt.rn.bf16x2.f32 %0, %1, %2;" : "=r"(r) : "f"(b), "f"(a));
    return r;
}
__device__ __forceinline__ void cpa16(uint32_t dst, const void* src, int sz) {
    asm volatile("cp.async.ca.shared.global [%0], [%1], 16, %2;"
                 :: "r"(dst), "l"(src), "r"(sz));
}
#define CP_COMMIT() asm volatile("cp.async.commit_group;" ::)
#define CP_WAIT1()  asm volatile("cp.async.wait_group 1;" ::)
#define CP_WAIT0()  asm volatile("cp.async.wait_group 0;" ::)

// ---------------------------------------------------------------------------
// GEMM: pre-split hi/lo bf16 operands, 3-stage cp.async pipeline,
// ONE __syncthreads per 32-K chunk.
// MODE 0: B = [b][k][hw] rows (k-major) + ldmatrix.trans.
// MODE 1: B = y1t [b][hw][256] rows (n-major), K = (kh*3+kw)*256 + ci.
// OUT 0: fp32 relu.  OUT 1: hi/lo bf16 relu.  OUT 2: fp32 + shuffled resid + relu.
// ---------------------------------------------------------------------------
template <int MODE, int OUT>
__global__ void __launch_bounds__(256, 2)
conv_mma3(const uint16_t* __restrict__ Ah, const uint16_t* __restrict__ Al,
          const uint16_t* __restrict__ Bh, const uint16_t* __restrict__ Bl,
          float* __restrict__ OutF, uint16_t* __restrict__ OutH, uint16_t* __restrict__ OutL,
          int Mout, int KTOT,
          const float* __restrict__ xres, const int* __restrict__ perm)
{
    extern __shared__ char smem[];
    const uint32_t sb = smem_to_u32(smem);
    const int tid = threadIdx.x, wid = tid >> 5, lane = tid & 31;
    const int mtile = blockIdx.y * MT, ctile = blockIdx.x * NT;

    constexpr int BT    = (MODE == 0) ? BT0 : BT1;
    constexpr int STAGE = ATILE + BT;

    // ---- A loader: row = tid>>1, 32B half = tid&1 ----
    const int arow = tid >> 1, apart = tid & 1;
    const uint16_t* aSrcH = Ah + (size_t)(mtile + arow) * KTOT + apart * 16;
    const uint16_t* aSrcL = Al + (size_t)(mtile + arow) * KTOT + apart * 16;
    const uint32_t aDstH = (uint32_t)arow * AR + apart * 32;

    // ---- B loader precompute ----
    int brow = 0, bsc0 = 0;
    size_t bOff0 = 0, bOff1 = 0;
    int nrow = 0, bpart = 0, boh = 0, bow = 0;
    size_t bBase = 0;
    if (MODE == 0) {
        brow = tid >> 3; bsc0 = (tid & 7) * 2;
        const int col0 = ctile + bsc0 * 8, col1 = col0 + 8;
        const int bb0 = col0 / HW, hw0 = col0 - bb0 * HW;
        const int bb1 = col1 / HW, hw1 = col1 - bb1 * HW;
        bOff0 = ((size_t)bb0 * KTOT + brow) * HW + hw0;
        bOff1 = ((size_t)bb1 * KTOT + brow) * HW + hw1;
    } else {
        nrow = tid >> 1; bpart = tid & 1;
        const int coln = ctile + nrow;
        const int bbn = coln / HW, hwn = coln - bbn * HW;
        boh = hwn / IMG_W; bow = hwn - boh * IMG_W;
        bBase = (size_t)bbn * HW * 256;
    }

    auto issue = [&](int c) {
        const uint32_t s0 = sb + (uint32_t)(c % 3) * STAGE;
        {   // A hi/lo into fused row
            const uint16_t* ph = aSrcH + (size_t)c * 32;
            const uint16_t* pl = aSrcL + (size_t)c * 32;
            const uint32_t d = s0 + aDstH;
            cpa16(d, ph, 16);         cpa16(d + 16, ph + 8, 16);
            cpa16(d + 64, pl, 16);    cpa16(d + 64 + 16, pl + 8, 16);
        }
        if (MODE == 0) {
            const size_t kadd = (size_t)c * 32 * HW;
            const uint32_t d = s0 + ATILE + (uint32_t)brow * BR0 + bsc0 * 16;
            cpa16(d,            Bh + bOff0 + kadd, 16);
            cpa16(d + 16,       Bh + bOff1 + kadd, 16);
            cpa16(d + 256,      Bl + bOff0 + kadd, 16);
            cpa16(d + 256 + 16, Bl + bOff1 + kadd, 16);
        } else {
            const int khkw = c >> 3, cib = (c & 7) * 32;
            const int kh = khkw / 3, kw = khkw - kh * 3;
            const int ih = boh + kh - 1, iw = bow + kw - 1;
            const bool ok = ((unsigned)ih < (unsigned)IMG_W) && ((unsigned)iw < (unsigned)IMG_W);
            const int sz = ok ? 16 : 0;
            const size_t off = ok ? (bBase + (size_t)(ih * IMG_W + iw) * 256 + cib + bpart * 16) : 0;
            const uint32_t d = s0 + ATILE + (uint32_t)nrow * BR1 + bpart * 32;
            cpa16(d,           Bh + off,     sz);
            cpa16(d + 16,      Bh + off + 8, sz);
            cpa16(d + 64,      Bl + off,     sz);
            cpa16(d + 64 + 16, Bl + off + 8, sz);
        }
    };

    // ---- fragment addressing ----
    const int warpM = (wid >> 1) * 32, warpN = (wid & 1) * 64;
    const uint32_t aRowOff = (uint32_t)(warpM + (lane & 15)) * AR + ((lane >> 4) & 1) * 16;
    uint32_t bFragOff;
    if (MODE == 0)
        bFragOff = (uint32_t)(lane & 15) * BR0 + (uint32_t)(warpN + (lane >> 4) * 8) * 2;
    else
        bFragOff = (uint32_t)(warpN + (lane & 7) + ((lane >> 4) & 1) * 8) * BR1
                 + ((lane >> 3) & 1) * 16;

    float acc[2][8][4];
#pragma unroll
    for (int i = 0; i < 2; i++)
#pragma unroll
        for (int j = 0; j < 8; j++)
#pragma unroll
            for (int q = 0; q < 4; q++) acc[i][j][q] = 0.f;

    const int NCH = KTOT / 32;

    issue(0); CP_COMMIT();
    issue(1); CP_COMMIT();

    for (int c = 0; c < NCH; c++) {
        if (c + 1 < NCH) CP_WAIT1();
        else             CP_WAIT0();
        __syncthreads();
        if (c + 2 < NCH) { issue(c + 2); CP_COMMIT(); }

        const uint32_t aB = sb + (uint32_t)(c % 3) * STAGE;
        const uint32_t bB = aB + ATILE;
#pragma unroll
        for (int ks = 0; ks < 2; ks++) {
            uint32_t ah[8], al[8];
            ldsm4(ah + 0, aB + aRowOff + ks * 32);
            ldsm4(ah + 4, aB + aRowOff + 16 * AR + ks * 32);
            ldsm4(al + 0, aB + aRowOff + 64 + ks * 32);
            ldsm4(al + 4, aB + aRowOff + 16 * AR + 64 + ks * 32);
#pragma unroll
            for (int np = 0; np < 4; np++) {
                uint32_t bh[4], bl[4];
                if (MODE == 0) {
                    const uint32_t o = bFragOff + ks * 16 * BR0 + np * 32;
                    ldsm4t(bh, bB + o);
                    ldsm4t(bl, bB + o + 256);
                } else {
                    const uint32_t o = bFragOff + np * 16 * BR1 + ks * 32;
                    ldsm4(bh, bB + o);
                    ldsm4(bl, bB + o + 64);
                }
#pragma unroll
                for (int mf = 0; mf < 2; mf++)
#pragma unroll
                    for (int t = 0; t < 2; t++) {
                        float* C = acc[mf][np * 2 + t];
                        mma_bf16(C, ah + mf * 4, bh + t * 2);
                        mma_bf16(C, ah + mf * 4, bl + t * 2);
                        mma_bf16(C, al + mf * 4, bh + t * 2);
                    }
            }
        }
    }

    // ---- epilogue ----
    const int mBase = mtile + warpM + (lane >> 2);
    const int nCol  = ctile + warpN + (lane & 3) * 2;
#pragma unroll
    for (int mf = 0; mf < 2; mf++) {
#pragma unroll
        for (int nf = 0; nf < 8; nf++) {
            const float* C = acc[mf][nf];
            const int n  = nCol + nf * 8;
            const int b2 = n / HW;
            const int hw = n - b2 * HW;
            const int m0 = mBase + mf * 16;
            const int m1 = m0 + 8;
            float v0 = C[0], v1 = C[1], v2 = C[2], v3 = C[3];
            if (OUT == 2) {
                const float* xr0 = xres + ((size_t)b2 * Mout + m0) * HW;
                const float* xr1 = xres + ((size_t)b2 * Mout + m1) * HW;
                const int* p0 = perm + (size_t)m0 * HW + hw;
                const int* p1 = perm + (size_t)m1 * HW + hw;
                v0 += xr0[p0[0]]; v1 += xr0[p0[1]];
                v2 += xr1[p1[0]]; v3 += xr1[p1[1]];
            }
            v0 = fmaxf(v0, 0.f); v1 = fmaxf(v1, 0.f);
            v2 = fmaxf(v2, 0.f); v3 = fmaxf(v3, 0.f);
            if (OUT == 1) {
                const size_t e0 = ((size_t)b2 * Mout + m0) * HW + hw;
                const size_t e1 = ((size_t)b2 * Mout + m1) * HW + hw;
                uint32_t h01 = pack_bf16x2(v0, v1);
                uint32_t l01 = pack_bf16x2(v0 - __uint_as_float(h01 << 16),
                                           v1 - __uint_as_float(h01 & 0xFFFF0000u));
                uint32_t h23 = pack_bf16x2(v2, v3);
                uint32_t l23 = pack_bf16x2(v2 - __uint_as_float(h23 << 16),
                                           v3 - __uint_as_float(h23 & 0xFFFF0000u));
                *(uint32_t*)(OutH + e0) = h01;
                *(uint32_t*)(OutL + e0) = l01;
                *(uint32_t*)(OutH + e1) = h23;
                *(uint32_t*)(OutL + e1) = l23;
            } else {
                *(float2*)(OutF + ((size_t)b2 * Mout + m0) * HW + hw) = make_float2(v0, v1);
                *(float2*)(OutF + ((size_t)b2 * Mout + m1) * HW + hw) = make_float2(v2, v3);
            }
        }
    }
}

// ---------------------------------------------------------------------------
// fp32 -> hi/lo bf16 split (pairwise, vectorized)
// ---------------------------------------------------------------------------
__global__ __launch_bounds__(256)
void cvt_split_kernel(const float* __restrict__ in, uint16_t* __restrict__ hi,
                      uint16_t* __restrict__ lo, long n2)
{
    long i = (long)blockIdx.x * blockDim.x + threadIdx.x;
    const long stride = (long)gridDim.x * blockDim.x;
    for (; i < n2; i += stride) {
        float2 v = ((const float2*)in)[i];
        uint32_t h = pack_bf16x2(v.x, v.y);
        uint32_t l = pack_bf16x2(v.x - __uint_as_float(h << 16),
                                 v.y - __uint_as_float(h & 0xFFFF0000u));
        ((uint32_t*)hi)[i] = h;
        ((uint32_t*)lo)[i] = l;
    }
}

// wd [co][ci][3][3] -> wdc [co][(kh*3+kw)*256 + ci], split hi/lo
__global__ __launch_bounds__(256)
void cvt_wd_kernel(const float* __restrict__ wd, uint16_t* __restrict__ hi,
                   uint16_t* __restrict__ lo)
{
    const long total = 256L * 2304;
    long o = (long)blockIdx.x * blockDim.x + threadIdx.x;
    const long stride = (long)gridDim.x * blockDim.x;
    for (; o < total; o += stride) {
        const int co = (int)(o / 2304);
        const int rr = (int)(o - (long)co * 2304);
        const int r  = rr >> 8;          // kh*3+kw
        const int ci = rr & 255;
        float v = wd[(size_t)co * 2304 + ci * 9 + r];
        uint32_t h = pack_bf16x2(v, 0.f);
        float hv = __uint_as_float(h << 16);
        uint32_t l = pack_bf16x2(v - hv, 0.f);
        hi[o] = (uint16_t)(h & 0xFFFFu);
        lo[o] = (uint16_t)(l & 0xFFFFu);
    }
}

// ---------------------------------------------------------------------------
// Fused shuffle + transpose + split: y1[b][c][perm[c][j]] -> y1t[b][j][c] hi/lo
// ---------------------------------------------------------------------------
__global__ __launch_bounds__(256)
void shuf_t_kernel(const float* __restrict__ y1, const int* __restrict__ perm,
                   uint16_t* __restrict__ outh, uint16_t* __restrict__ outl)
{
    __shared__ uint16_t sh[28][264];
    __shared__ uint16_t sl[28][264];
    const int tid = threadIdx.x, wid = tid >> 5, lane = tid & 31;
    const int b  = blockIdx.y;
    const int j0 = blockIdx.x * 28;

    if (lane < 28) {
#pragma unroll 4
        for (int it = 0; it < 32; it++) {
            const int c = wid + it * 8;
            const int p = perm[(size_t)c * HW + j0 + lane];
            const float v = y1[((size_t)b * 256 + c) * HW + p];
            uint32_t h = pack_bf16x2(v, 0.f);
            float hv = __uint_as_float(h << 16);
            uint32_t l = pack_bf16x2(v - hv, 0.f);
            sh[lane][c] = (uint16_t)(h & 0xFFFFu);
            sl[lane][c] = (uint16_t)(l & 0xFFFFu);
        }
    }
    __syncthreads();

#pragma unroll
    for (int it = 0; it < 4; it++) {
        const int idx = tid + it * 256;
        if (idx < 28 * 32) {
            const int j = idx >> 5, s = idx & 31;
            const size_t e = ((size_t)b * HW + j0 + j) * 256 + s * 8;
            *(uint4*)(outh + e) = *(const uint4*)&sh[j][s * 8];
            *(uint4*)(outl + e) = *(const uint4*)&sl[j][s * 8];
        }
    }
}

// ---------------------------------------------------------------------------
extern "C" void kernel_launch(void* const* d_in, const int* in_sizes, int n_in,
                              void* d_out, int out_size)
{
    const float* x  = (const float*)d_in[0];   // [32,1024,28,28]
    const float* w1 = (const float*)d_in[1];   // [256,1024,1,1]
    const float* wd = (const float*)d_in[2];   // [256,256,3,3]
    const float* w3 = (const float*)d_in[3];   // [1024,256,1,1]
    const int*   pd = (const int*)d_in[4];     // [256,784]
    const int*   pr = (const int*)d_in[5];     // [1024,784]
    float*       out = (float*)d_out;          // [32,1024,28,28]

    float* y1;
    uint16_t *xh, *xl, *w1h, *w1l, *wdh, *wdl, *w3h, *w3l, *y1th, *y1tl, *y2h, *y2l;
    cudaGetSymbolAddress((void**)&y1,   g_y1);
    cudaGetSymbolAddress((void**)&xh,   g_xh);
    cudaGetSymbolAddress((void**)&xl,   g_xl);
    cudaGetSymbolAddress((void**)&w1h,  g_w1h);
    cudaGetSymbolAddress((void**)&w1l,  g_w1l);
    cudaGetSymbolAddress((void**)&wdh,  g_wdh);
    cudaGetSymbolAddress((void**)&wdl,  g_wdl);
    cudaGetSymbolAddress((void**)&w3h,  g_w3h);
    cudaGetSymbolAddress((void**)&w3l,  g_w3l);
    cudaGetSymbolAddress((void**)&y1th, g_y1th);
    cudaGetSymbolAddress((void**)&y1tl, g_y1tl);
    cudaGetSymbolAddress((void**)&y2h,  g_y2h);
    cudaGetSymbolAddress((void**)&y2l,  g_y2l);

    const int SM0 = 3 * (ATILE + BT0);   // 105984
    const int SM1 = 3 * (ATILE + BT1);   // 110592
    cudaFuncSetAttribute(conv_mma3<0, 0>, cudaFuncAttributeMaxDynamicSharedMemorySize, SM0);
    cudaFuncSetAttribute(conv_mma3<1, 1>, cudaFuncAttributeMaxDynamicSharedMemorySize, SM1);
    cudaFuncSetAttribute(conv_mma3<0, 2>, cudaFuncAttributeMaxDynamicSharedMemorySize, SM0);

    // 0) precompute: split x and weights to hi/lo bf16
    cvt_split_kernel<<<4736, 256>>>(x, xh, xl, 32L * 1024 * HW / 2);
    cvt_split_kernel<<<512, 256>>>(w1, w1h, w1l, 256L * 1024 / 2);
    cvt_split_kernel<<<512, 256>>>(w3, w3h, w3l, 1024L * 256 / 2);
    cvt_wd_kernel<<<1024, 256>>>(wd, wdh, wdl);

    // 1) conv1 (1x1, 1024->256) + relu -> y1 fp32
    {
        dim3 grid(NTOT / NT, 2);
        conv_mma3<0, 0><<<grid, 256, SM0>>>(w1h, w1l, xh, xl,
                                            y1, nullptr, nullptr, 256, 1024,
                                            nullptr, nullptr);
    }
    // 2) shuffle + transpose + split -> y1t hi/lo
    {
        dim3 grid(HW / 28, 32);
        shuf_t_kernel<<<grid, 256>>>(y1, pd, y1th, y1tl);
    }
    // 3) 3x3 conv (256->256, pad 1) + relu -> y2 hi/lo bf16
    {
        dim3 grid(NTOT / NT, 2);
        conv_mma3<1, 1><<<grid, 256, SM1>>>(wdh, wdl, y1th, y1tl,
                                            nullptr, y2h, y2l, 256, 2304,
                                            nullptr, nullptr);
    }
    // 4) conv3 (1x1, 256->1024) + shuffled residual + relu -> out
    {
        dim3 grid(NTOT / NT, 8);
        conv_mma3<0, 2><<<grid, 256, SM0>>>(w3h, w3l, y2h, y2l,
                                            out, nullptr, nullptr, 1024, 256,
                                            x, pr);
    }
}